// round 16
// baseline (speedup 1.0000x reference)
#include <cuda_runtime.h>
#include <math.h>

// output_spikes (B=16, T=2000, N=512) float32, target_cv (512) float32.
#define NNEUR 512
#define NG    128                  // neuron groups of 4 (float4)
#define LTOT  32000                // B*T
#define NBLK  296                  // 2 blocks/SM, single wave
#define SUBS  (NBLK * 4)           // 1184 sub-chunks (4 row-slices per block)
#define RB    (LTOT / SUBS)        // 27
#define RREM  (LTOT % SUBS)        // 32 (sub-chunks 0..31 get 28 rows)

typedef unsigned long long u64;

// packed {1.0f,1.0f} and {-1.0f,-1.0f}
#define ONE2_C   0x3F8000003F800000ULL
#define NEG12_C  0xBF800000BF800000ULL

#define F2_ADD(o, a, b)    asm("add.rn.f32x2 %0, %1, %2;" : "=l"(o) : "l"(a), "l"(b))
#define F2_MUL(o, a, b)    asm("mul.rn.f32x2 %0, %1, %2;" : "=l"(o) : "l"(a), "l"(b))
#define F2_FMA(o, a, b, c) asm("fma.rn.f32x2 %0, %1, %2, %3;" : "=l"(o) : "l"(a), "l"(b), "l"(c))
#define F2_PACK(o, lo, hi) asm("mov.b64 %0, {%1, %2};" : "=l"(o) : "f"(lo), "f"(hi))
#define F2_UNPACK(lo, hi, in) asm("mov.b64 {%0, %1}, %2;" : "=f"(lo), "=f"(hi) : "l"(in))

// Per-(neuron, block) partial: {k, first_spike_l, last_spike_l, bits(sum_d2)}
__device__ int4  g_partial[NNEUR * NBLK];
__device__ float g_accum;     // reset by block 0 at launch start (ordered by barrier)
__device__ int   g_cnt;
__device__ int   g_ticket;
__device__ int   g_bar;       // grid barrier; reset by publisher at end of launch

// Ordered combine of two ADJACENT segments (a before b). Identity: k == 0.
__device__ __forceinline__ int4 comb(int4 a, int4 b) {
    if (b.x == 0) return a;
    if (a.x == 0) return b;
    float d = (float)(b.y - a.z);                       // cross-segment ISI
    float s = __int_as_float(a.w) + __int_as_float(b.w) + d * d;
    return make_int4(a.x + b.x, a.y, b.z, __float_as_int(s));
}

// Packed update for one neuron pair p. v in {0,1} per lane.
#define PEP(p, vlo, vhi)                         \
    do {                                         \
        u64 v2_, d2_, m2_, t2_;                  \
        F2_PACK(v2_, (vlo), (vhi));              \
        F2_ADD(d2_, gp2[p], one2);               \
        F2_MUL(m2_, v2_, d2_);                   \
        F2_FMA(s2[p], m2_, d2_, s2[p]);          \
        F2_FMA(gp2[p], m2_, neg12, d2_);         \
        F2_ADD(kf2[p], kf2[p], v2_);             \
        F2_MUL(t2_, v2_, ns2[p]);                \
        F2_FMA(ns2[p], t2_, neg12, ns2[p]);      \
        F2_ADD(lz2[p], lz2[p], ns2[p]);          \
    } while (0)

#define PROW(vec)                      \
    do {                               \
        PEP(0, (vec).x, (vec).y);      \
        PEP(1, (vec).z, (vec).w);      \
    } while (0)

__global__ __launch_bounds__(512, 2) void cvl_fused(const float* __restrict__ x,
                                                    const float* __restrict__ target,
                                                    float* __restrict__ out) {
    const int tid   = threadIdx.x;
    const int wid   = tid >> 5;
    const int lane  = tid & 31;
    const int slice = tid >> 7;          // 0..3 : row-slice within block
    const int g     = tid & (NG - 1);    // 0..127: neuron group (4 neurons)
    const int sc    = blockIdx.x * 4 + slice;      // global sub-chunk
    if (blockIdx.x == 0 && tid == 0) { g_accum = 0.0f; g_cnt = 0; g_ticket = 0; }

    // ---------------- Phase 1: scan ----------------
    const int start = sc * RB + min(sc, RREM);
    const int rows  = RB + (sc < RREM ? 1 : 0);    // 27 or 28

    const u64 one2  = ONE2_C;
    const u64 neg12 = NEG12_C;
    u64 gp2[2] = {0ULL, 0ULL};
    u64 s2[2]  = {0ULL, 0ULL};
    u64 kf2[2] = {0ULL, 0ULL};
    u64 ns2[2] = {ONE2_C, ONE2_C};
    u64 lz2[2] = {0ULL, 0ULL};

    const float4* p = (const float4*)x + (size_t)start * NG + g;
    int r = 0;

    float4 b0 = __ldg(p + 0 * NG), b1 = __ldg(p + 1 * NG);
    float4 b2 = __ldg(p + 2 * NG), b3 = __ldg(p + 3 * NG);
    p += 4 * NG;

    while (r + 8 <= rows) {
        float4 c0 = __ldg(p + 0 * NG), c1 = __ldg(p + 1 * NG);
        float4 c2 = __ldg(p + 2 * NG), c3 = __ldg(p + 3 * NG);
        p += 4 * NG;
        PROW(b0); PROW(b1); PROW(b2); PROW(b3);
        b0 = c0; b1 = c1; b2 = c2; b3 = c3;
        r += 4;
    }
    PROW(b0); PROW(b1); PROW(b2); PROW(b3);
    r += 4;
    for (; r < rows; ++r) {
        float4 v = __ldg(p);
        p += NG;
        PROW(v);
    }

    // Flush to smem, combine 4 slices, store per-block partials.
    __shared__ int4 sp[4][NNEUR];
#pragma unroll
    for (int pr = 0; pr < 2; ++pr) {
        float kfl, kfh, gpl, gph, ssl, ssh, lzl, lzh;
        F2_UNPACK(kfl, kfh, kf2[pr]);
        F2_UNPACK(gpl, gph, gp2[pr]);
        F2_UNPACK(ssl, ssh, s2[pr]);
        F2_UNPACK(lzl, lzh, lz2[pr]);
        float kfj[2] = {kfl, kfh}, gpj[2] = {gpl, gph};
        float ssj[2] = {ssl, ssh}, lzj[2] = {lzl, lzh};
#pragma unroll
        for (int h = 0; h < 2; ++h) {
            const int j = pr * 2 + h;
            int kk = (int)kfj[h];
            int4 part;
            if (kk > 0) {
                float tf1 = lzj[h] + 1.0f;            // t_first, 1-based local
                int tlast = rows - (int)gpj[h];       // 1-based local
                float sc_ = ssj[h] - tf1 * tf1;
                part = make_int4(kk, start + (int)lzj[h], start + tlast - 1,
                                 __float_as_int(sc_));
            } else {
                part = make_int4(0, 0, 0, 0);
            }
            sp[slice][g * 4 + j] = part;
        }
    }
    __syncthreads();

    if (slice == 0) {
#pragma unroll
        for (int j = 0; j < 4; ++j) {
            const int n = g * 4 + j;
            int4 a = sp[0][n];
            a = comb(a, sp[1][n]);
            a = comb(a, sp[2][n]);
            a = comb(a, sp[3][n]);
            g_partial[(size_t)n * NBLK + blockIdx.x] = a;
        }
    }
    __syncthreads();

    // ---------------- Grid barrier arrival ----------------
    if (tid == 0) {
        __threadfence();                       // partials visible device-wide
        atomicAdd(&g_bar, 1);
    }

    // Blocks >= 32 are done.
    if (blockIdx.x >= 32) return;

    // ---------------- Phase 2: reduce (blocks 0..31) ----------------
    if (tid == 0) {
        while (atomicAdd(&g_bar, 0) < NBLK)    // spin until all scans landed
            __nanosleep(64);
    }
    __syncthreads();
    __threadfence();                           // acquire: order loads after barrier

    // warp-per-neuron: 32 blocks x 16 warps = 512 warps
    const int n = blockIdx.x * 16 + wid;       // neuron

    // contiguous lane partition of 296 = 8*10 + 24*9
    const int cnt   = (lane < 8) ? 10 : 9;
    const int begin = lane * 9 + min(lane, 8);

    const int4* base = &g_partial[(size_t)n * NBLK + begin];
    int4 acc = base[0];
#pragma unroll
    for (int i = 1; i < 9; ++i)
        acc = comb(acc, base[i]);
    if (cnt == 10)
        acc = comb(acc, base[9]);

    // shfl adjacent-pair tree: offsets 1,2,4,8,16 (lane order = segment order)
#pragma unroll
    for (int off = 1; off < 32; off <<= 1) {
        int4 other;
        other.x = __shfl_down_sync(0xFFFFFFFFu, acc.x, off);
        other.y = __shfl_down_sync(0xFFFFFFFFu, acc.y, off);
        other.z = __shfl_down_sync(0xFFFFFFFFu, acc.z, off);
        other.w = __shfl_down_sync(0xFFFFFFFFu, acc.w, off);
        int4 res = comb(acc, other);
        if ((lane & (2 * off - 1)) == 0)
            acc = res;
    }

    if (lane == 0) {
        int kk = acc.x;
        if (kk >= 3) {
            float cnt_f = (float)(kk - 1);            // number of ISIs
            float sum_d = (float)(acc.z - acc.y);     // telescoping sum of ISIs
            float mean  = sum_d / cnt_f;
            if (mean > 0.0f) {
                // sum((d-mean)^2) = sum_d2 - 2*mean*sum_d + cnt*mean^2
                float var = (__int_as_float(acc.w) - 2.0f * mean * sum_d + cnt_f * mean * mean)
                            / fmaxf(cnt_f - 1.0f, 1.0f);   // unbiased (correction=1)
                float stdv = (var > 0.0f) ? sqrtf(var) : 0.0f;
                float cv   = stdv / fmaxf(mean, 1e-12f);
                float diff = cv - target[n];
                atomicAdd(&g_accum, diff * diff);
                atomicAdd(&g_cnt, 1);
            }
        }
        // Ticket: the last of the 512 reduce warps publishes and resets g_bar
        // for the next (graph-replayed) launch. Safe: all spinners have passed
        // the barrier before ticket 511 can occur, and the next launch starts
        // only after this kernel fully retires.
        __threadfence();
        int t = atomicAdd(&g_ticket, 1);
        if (t == NNEUR - 1) {
            float acc_s = atomicAdd(&g_accum, 0.0f);   // coherent L2 read
            int   c     = atomicAdd(&g_cnt, 0);
            out[0] = acc_s / fmaxf((float)c, 1.0f);
            g_bar = 0;
            __threadfence();
        }
    }
}

extern "C" void kernel_launch(void* const* d_in, const int* in_sizes, int n_in,
                              void* d_out, int out_size) {
    const float* spikes = (const float*)d_in[0];   // (16, 2000, 512) float32
    const float* target = (const float*)d_in[1];   // (512,) float32
    float* out = (float*)d_out;                    // scalar float32

    cvl_fused<<<NBLK, 512>>>(spikes, target, out);
}

// round 17
// speedup vs baseline: 1.0122x; 1.0122x over previous
#include <cuda_runtime.h>
#include <math.h>

// output_spikes (B=16, T=2000, N=512) float32, target_cv (512) float32.
#define NNEUR 512
#define NG    128                  // neuron groups of 4 (float4)
#define LTOT  32000                // B*T
#define NBLK  296                  // 2 blocks/SM, single wave
#define SUBS  (NBLK * 4)           // 1184 sub-chunks (4 row-slices per block)
#define RB    (LTOT / SUBS)        // 27
// remainder 32 rows spread over sub-chunks sc % 37 == 0 (one per 37 -> at most
// one 28-row slice per block, max block load 109 rows instead of 112)

typedef unsigned long long u64;

// packed {1.0f,1.0f} and {-1.0f,-1.0f}
#define ONE2_C   0x3F8000003F800000ULL
#define NEG12_C  0xBF800000BF800000ULL

#define F2_ADD(o, a, b)    asm("add.rn.f32x2 %0, %1, %2;" : "=l"(o) : "l"(a), "l"(b))
#define F2_MUL(o, a, b)    asm("mul.rn.f32x2 %0, %1, %2;" : "=l"(o) : "l"(a), "l"(b))
#define F2_FMA(o, a, b, c) asm("fma.rn.f32x2 %0, %1, %2, %3;" : "=l"(o) : "l"(a), "l"(b), "l"(c))
#define F2_PACK(o, lo, hi) asm("mov.b64 %0, {%1, %2};" : "=l"(o) : "f"(lo), "f"(hi))
#define F2_UNPACK(lo, hi, in) asm("mov.b64 {%0, %1}, %2;" : "=f"(lo), "=f"(hi) : "l"(in))

// Per-(neuron, block) partial: {k, first_spike_l, last_spike_l, bits(sum_d2)}
__device__ int4  g_partial[NNEUR * NBLK];
__device__ float g_accum;
__device__ int   g_cnt;
__device__ int   g_ticket;

// Ordered combine of two ADJACENT segments (a before b). Identity: k == 0.
__device__ __forceinline__ int4 comb(int4 a, int4 b) {
    if (b.x == 0) return a;
    if (a.x == 0) return b;
    float d = (float)(b.y - a.z);                       // cross-segment ISI
    float s = __int_as_float(a.w) + __int_as_float(b.w) + d * d;
    return make_int4(a.x + b.x, a.y, b.z, __float_as_int(s));
}

// Packed update for one neuron pair p. v in {0,1} per lane.
#define PEP(p, vlo, vhi)                         \
    do {                                         \
        u64 v2_, d2_, m2_, t2_;                  \
        F2_PACK(v2_, (vlo), (vhi));              \
        F2_ADD(d2_, gp2[p], one2);               \
        F2_MUL(m2_, v2_, d2_);                   \
        F2_FMA(s2[p], m2_, d2_, s2[p]);          \
        F2_FMA(gp2[p], m2_, neg12, d2_);         \
        F2_ADD(kf2[p], kf2[p], v2_);             \
        F2_MUL(t2_, v2_, ns2[p]);                \
        F2_FMA(ns2[p], t2_, neg12, ns2[p]);      \
        F2_ADD(lz2[p], lz2[p], ns2[p]);          \
    } while (0)

#define PROW(vec)                      \
    do {                               \
        PEP(0, (vec).x, (vec).y);      \
        PEP(1, (vec).z, (vec).w);      \
    } while (0)

__global__ __launch_bounds__(512, 2) void cvl_scan(const float* __restrict__ x) {
    const int tid   = threadIdx.x;
    const int slice = tid >> 7;          // 0..3 : row-slice within block
    const int g     = tid & (NG - 1);    // 0..127: neuron group (4 neurons)
    const int sc    = blockIdx.x * 4 + slice;      // global sub-chunk
    if (blockIdx.x == 0 && tid == 0) { g_accum = 0.0f; g_cnt = 0; g_ticket = 0; }

    // balanced distribution: sub-chunks sc % 37 == 0 get one extra row
    const int start = sc * RB + (sc + 36) / 37;
    const int rows  = RB + ((sc % 37) == 0 ? 1 : 0);   // 27 or 28

    const u64 one2  = ONE2_C;
    const u64 neg12 = NEG12_C;
    u64 gp2[2] = {0ULL, 0ULL};
    u64 s2[2]  = {0ULL, 0ULL};
    u64 kf2[2] = {0ULL, 0ULL};
    u64 ns2[2] = {ONE2_C, ONE2_C};
    u64 lz2[2] = {0ULL, 0ULL};

    const float4* p = (const float4*)x + (size_t)start * NG + g;
    int r = 0;

    // prefetch batch 0 (rows >= 27 > 4 always); nc/texture path
    float4 b0 = __ldg(p + 0 * NG), b1 = __ldg(p + 1 * NG);
    float4 b2 = __ldg(p + 2 * NG), b3 = __ldg(p + 3 * NG);
    p += 4 * NG;

    while (r + 8 <= rows) {
        float4 c0 = __ldg(p + 0 * NG), c1 = __ldg(p + 1 * NG);
        float4 c2 = __ldg(p + 2 * NG), c3 = __ldg(p + 3 * NG);
        p += 4 * NG;
        PROW(b0); PROW(b1); PROW(b2); PROW(b3);
        b0 = c0; b1 = c1; b2 = c2; b3 = c3;
        r += 4;
    }
    PROW(b0); PROW(b1); PROW(b2); PROW(b3);
    r += 4;
    for (; r < rows; ++r) {
        float4 v = __ldg(p);
        p += NG;
        PROW(v);
    }

    // Flush: t_first = lz+1, t_last = rows - gp (1-based local);
    // subtract bogus first gap^2 (= t_first^2) from s.
    __shared__ int4 sp[4][NNEUR];
#pragma unroll
    for (int pr = 0; pr < 2; ++pr) {
        float kfl, kfh, gpl, gph, ssl, ssh, lzl, lzh;
        F2_UNPACK(kfl, kfh, kf2[pr]);
        F2_UNPACK(gpl, gph, gp2[pr]);
        F2_UNPACK(ssl, ssh, s2[pr]);
        F2_UNPACK(lzl, lzh, lz2[pr]);
        float kfj[2] = {kfl, kfh}, gpj[2] = {gpl, gph};
        float ssj[2] = {ssl, ssh}, lzj[2] = {lzl, lzh};
#pragma unroll
        for (int h = 0; h < 2; ++h) {
            const int j = pr * 2 + h;
            int kk = (int)kfj[h];
            int4 part;
            if (kk > 0) {
                float tf1 = lzj[h] + 1.0f;            // t_first, 1-based local
                int tlast = rows - (int)gpj[h];       // 1-based local
                float sc_ = ssj[h] - tf1 * tf1;
                part = make_int4(kk, start + (int)lzj[h], start + tlast - 1,
                                 __float_as_int(sc_));
            } else {
                part = make_int4(0, 0, 0, 0);
            }
            sp[slice][g * 4 + j] = part;
        }
    }
    __syncthreads();

    if (slice == 0) {
#pragma unroll
        for (int j = 0; j < 4; ++j) {
            const int n = g * 4 + j;
            int4 a = sp[0][n];
            a = comb(a, sp[1][n]);
            a = comb(a, sp[2][n]);
            a = comb(a, sp[3][n]);
            g_partial[(size_t)n * NBLK + blockIdx.x] = a;
        }
    }
    __syncthreads();

    // PDL: make this block's writes visible, then allow the dependent
    // reduce kernel to proceed once all blocks have triggered/completed.
    __threadfence();
    cudaTriggerProgrammaticLaunchCompletion();
}

// Warp-per-neuron reduction: each lane serially folds a contiguous run of
// partials (lanes 0..7: 10, lanes 8..31: 9 -> 296), then a 5-step shfl tree
// (lane order = segment order, so the ordered combine stays valid).
__global__ __launch_bounds__(256) void cvl_reduce(const float* __restrict__ target,
                                                  float* __restrict__ out) {
    const int wid  = threadIdx.x >> 5;             // warp in block: 0..7
    const int lane = threadIdx.x & 31;
    const int n    = blockIdx.x * 8 + wid;         // neuron

    // contiguous lane partition of 296 = 8*10 + 24*9
    const int cnt   = (lane < 8) ? 10 : 9;
    const int begin = lane * 9 + min(lane, 8);
    const int4* base = &g_partial[(size_t)n * NBLK + begin];

    // PDL: wait for the scan grid before touching its outputs.
    cudaGridDependencySynchronize();

    int4 acc = base[0];
#pragma unroll
    for (int i = 1; i < 9; ++i)
        acc = comb(acc, base[i]);
    if (cnt == 10)
        acc = comb(acc, base[9]);

    // shfl adjacent-pair tree: offsets 1,2,4,8,16
#pragma unroll
    for (int off = 1; off < 32; off <<= 1) {
        int4 other;
        other.x = __shfl_down_sync(0xFFFFFFFFu, acc.x, off);
        other.y = __shfl_down_sync(0xFFFFFFFFu, acc.y, off);
        other.z = __shfl_down_sync(0xFFFFFFFFu, acc.z, off);
        other.w = __shfl_down_sync(0xFFFFFFFFu, acc.w, off);
        int4 res = comb(acc, other);
        if ((lane & (2 * off - 1)) == 0)
            acc = res;
    }

    if (lane == 0) {
        int kk = acc.x;
        if (kk >= 3) {
            float cnt_f = (float)(kk - 1);            // number of ISIs
            float sum_d = (float)(acc.z - acc.y);     // telescoping sum of ISIs
            float mean  = sum_d / cnt_f;
            if (mean > 0.0f) {
                // sum((d-mean)^2) = sum_d2 - 2*mean*sum_d + cnt*mean^2
                float var = (__int_as_float(acc.w) - 2.0f * mean * sum_d + cnt_f * mean * mean)
                            / fmaxf(cnt_f - 1.0f, 1.0f);   // unbiased (correction=1)
                float stdv = (var > 0.0f) ? sqrtf(var) : 0.0f;
                float cv   = stdv / fmaxf(mean, 1e-12f);
                float diff = cv - target[n];
                atomicAdd(&g_accum, diff * diff);
                atomicAdd(&g_cnt, 1);
            }
        }
        // Ticket: the last warp to pass here publishes the result.
        __threadfence();
        int t = atomicAdd(&g_ticket, 1);
        if (t == NNEUR - 1) {
            float acc_s = atomicAdd(&g_accum, 0.0f);   // coherent L2 read
            int   c     = atomicAdd(&g_cnt, 0);
            out[0] = acc_s / fmaxf((float)c, 1.0f);
        }
    }
}

extern "C" void kernel_launch(void* const* d_in, const int* in_sizes, int n_in,
                              void* d_out, int out_size) {
    const float* spikes = (const float*)d_in[0];   // (16, 2000, 512) float32
    const float* target = (const float*)d_in[1];   // (512,) float32
    float* out = (float*)d_out;                    // scalar float32

    cvl_scan<<<NBLK, 512>>>(spikes);

    // Reduce launched with programmatic dependent launch: it comes up while
    // the scan drains and blocks in cudaGridDependencySynchronize().
    cudaLaunchConfig_t cfg = {};
    cfg.gridDim  = dim3(NNEUR / 8, 1, 1);
    cfg.blockDim = dim3(256, 1, 1);
    cudaLaunchAttribute attrs[1];
    attrs[0].id = cudaLaunchAttributeProgrammaticStreamSerialization;
    attrs[0].val.programmaticStreamSerializationAllowed = 1;
    cfg.attrs    = attrs;
    cfg.numAttrs = 1;
    cudaLaunchKernelEx(&cfg, cvl_reduce, target, (float*)d_out);
}